// round 12
// baseline (speedup 1.0000x reference)
#include <cuda_runtime.h>
#include <cstdint>

// Problem constants
#define B_ 16
#define K_ 49
#define T_ 256
#define H_ 512
#define D_ 512

// Output packing: (c_hat_t, alpha_t, beta_t) flattened in order
#define OUT_ALPHA (B_ * T_ * H_)              // 2097152
#define OUT_BETA  (OUT_ALPHA + B_ * T_ * K_)  // 2297856

// Scratch: stores exp(2 * (linear + bias)) for every element.
// tanh(a+b) is then 1 - 2/(ea*eb + 1): no tanh in the hot loop at all.
__device__ float g_cv[B_ * K_ * D_];   // exp(2*(V@Wv + bv))
__device__ float g_cg[B_ * T_ * D_];   // exp(2*(h_t@Wg + bg))
__device__ float g_cs[B_ * T_ * D_];   // exp(2*(s_t@Ws + bs))

#define TWO_LOG2E 2.8853900817779268f

__device__ __forceinline__ float ex2a(float x)
{ float r; asm("ex2.approx.f32 %0, %1;" : "=f"(r) : "f"(x)); return r; }
__device__ __forceinline__ float rcpa(float x)
{ float r; asm("rcp.approx.f32 %0, %1;" : "=f"(r) : "f"(x)); return r; }

// ---------------------------------------------------------------------------
// Merged TF32 mma.sync GEMM: all three C[M,512] = exp(2*(A@W + bias)).
// ---------------------------------------------------------------------------
__global__ __launch_bounds__(256)
void gemm3_tf32_kernel(const float* __restrict__ V, const float* __restrict__ h_t,
                       const float* __restrict__ s_t,
                       const float* __restrict__ Wv, const float* __restrict__ bv,
                       const float* __restrict__ Wg, const float* __restrict__ bg,
                       const float* __restrict__ Wss, const float* __restrict__ bss)
{
    __shared__ float As[128 * 32];     // [m][k], k index xor-swizzled by 4*(m&7)
    __shared__ float Bs[32 * 136];     // [k][n], row stride 136 (pad 8)

    const int nt = blockIdx.x;         // 0..3
    int mt = blockIdx.y;               // 0..70
    const float *A, *W, *bias;
    float* C;
    int M;
    if (mt < 7)       { A = V;   W = Wv;  bias = bv;  C = g_cv; M = B_ * K_; }
    else if (mt < 39) { A = h_t; W = Wg;  bias = bg;  C = g_cg; M = B_ * T_; mt -= 7; }
    else              { A = s_t; W = Wss; bias = bss; C = g_cs; M = B_ * T_; mt -= 39; }

    const int tid  = threadIdx.x;
    const int lane = tid & 31;
    const int wid  = tid >> 5;
    const int g    = lane >> 2;
    const int tg   = lane & 3;
    const int warp_m = (wid >> 2) * 64;
    const int warp_n = (wid & 3) * 32;

    const int mbase = mt * 128;
    const int nbase = nt * 128;

    float acc[4][4][4];
    #pragma unroll
    for (int i = 0; i < 4; i++)
        #pragma unroll
        for (int j = 0; j < 4; j++)
            #pragma unroll
            for (int q = 0; q < 4; q++) acc[i][j][q] = 0.f;

    const int a_m0 = tid >> 3;
    const int a_k4 = (tid & 7) * 4;
    const int w_k0 = tid >> 5;
    const int w_n4 = (tid & 31) * 4;

    float4 pa[4], pw[4];

    #pragma unroll
    for (int i = 0; i < 4; i++) {
        const int row = mbase + a_m0 + i * 32;
        pa[i] = (row < M) ? *reinterpret_cast<const float4*>(&A[(size_t)row * 512 + a_k4])
                          : make_float4(0.f, 0.f, 0.f, 0.f);
        pw[i] = *reinterpret_cast<const float4*>(&W[(size_t)(w_k0 + i * 8) * 512 + nbase + w_n4]);
    }
    #pragma unroll
    for (int i = 0; i < 4; i++) {
        const int m = a_m0 + i * 32;
        *reinterpret_cast<float4*>(&As[m * 32 + (a_k4 ^ (4 * (m & 7)))]) = pa[i];
        *reinterpret_cast<float4*>(&Bs[(w_k0 + i * 8) * 136 + w_n4]) = pw[i];
    }
    __syncthreads();

    const int sw = 4 * g;

    for (int kt = 0; kt < 512; kt += 32) {
        if (kt + 32 < 512) {
            #pragma unroll
            for (int i = 0; i < 4; i++) {
                const int row = mbase + a_m0 + i * 32;
                pa[i] = (row < M) ? *reinterpret_cast<const float4*>(&A[(size_t)row * 512 + kt + 32 + a_k4])
                                  : make_float4(0.f, 0.f, 0.f, 0.f);
                pw[i] = *reinterpret_cast<const float4*>(&W[(size_t)(kt + 32 + w_k0 + i * 8) * 512 + nbase + w_n4]);
            }
        }

        #pragma unroll
        for (int kb = 0; kb < 32; kb += 8) {
            uint32_t af[4][4], bf[4][2];
            #pragma unroll
            for (int mi = 0; mi < 4; mi++) {
                const int m0 = warp_m + mi * 16;
                const int k0 = (kb + tg) ^ sw;
                const int k1 = (kb + tg + 4) ^ sw;
                af[mi][0] = __float_as_uint(As[(m0 + g)     * 32 + k0]);
                af[mi][1] = __float_as_uint(As[(m0 + g + 8) * 32 + k0]);
                af[mi][2] = __float_as_uint(As[(m0 + g)     * 32 + k1]);
                af[mi][3] = __float_as_uint(As[(m0 + g + 8) * 32 + k1]);
            }
            #pragma unroll
            for (int ni = 0; ni < 4; ni++) {
                const int n_ = warp_n + ni * 8 + g;
                bf[ni][0] = __float_as_uint(Bs[(kb + tg)     * 136 + n_]);
                bf[ni][1] = __float_as_uint(Bs[(kb + tg + 4) * 136 + n_]);
            }
            #pragma unroll
            for (int mi = 0; mi < 4; mi++)
                #pragma unroll
                for (int ni = 0; ni < 4; ni++) {
                    asm volatile(
                        "mma.sync.aligned.m16n8k8.row.col.f32.tf32.tf32.f32 "
                        "{%0,%1,%2,%3}, {%4,%5,%6,%7}, {%8,%9}, {%0,%1,%2,%3};"
                        : "+f"(acc[mi][ni][0]), "+f"(acc[mi][ni][1]),
                          "+f"(acc[mi][ni][2]), "+f"(acc[mi][ni][3])
                        : "r"(af[mi][0]), "r"(af[mi][1]), "r"(af[mi][2]), "r"(af[mi][3]),
                          "r"(bf[ni][0]), "r"(bf[ni][1]));
                }
        }
        __syncthreads();
        if (kt + 32 < 512) {
            #pragma unroll
            for (int i = 0; i < 4; i++) {
                const int m = a_m0 + i * 32;
                *reinterpret_cast<float4*>(&As[m * 32 + (a_k4 ^ (4 * (m & 7)))]) = pa[i];
                *reinterpret_cast<float4*>(&Bs[(w_k0 + i * 8) * 136 + w_n4]) = pw[i];
            }
            __syncthreads();
        }
    }

    // Epilogue: bias then exp(2x) via ex2.
    #pragma unroll
    for (int mi = 0; mi < 4; mi++) {
        const int r0 = mbase + warp_m + mi * 16 + g;
        const int r1 = r0 + 8;
        #pragma unroll
        for (int ni = 0; ni < 4; ni++) {
            const int c = nbase + warp_n + ni * 8 + tg * 2;
            const float2 bv2 = *reinterpret_cast<const float2*>(&bias[c]);
            float o00 = ex2a((acc[mi][ni][0] + bv2.x) * TWO_LOG2E);
            float o01 = ex2a((acc[mi][ni][1] + bv2.y) * TWO_LOG2E);
            float o10 = ex2a((acc[mi][ni][2] + bv2.x) * TWO_LOG2E);
            float o11 = ex2a((acc[mi][ni][3] + bv2.y) * TWO_LOG2E);
            if (r0 < M)
                *reinterpret_cast<float2*>(&C[(size_t)r0 * 512 + c]) = make_float2(o00, o01);
            if (r1 < M)
                *reinterpret_cast<float2*>(&C[(size_t)r1 * 512 + c]) = make_float2(o10, o11);
        }
    }
}

// Lane partial of S = sum_d wh[d] / (ev[d]*eg[d] + 1).
// Per element: MUL, ADD, RCP (rt-8 MUFU), FMA — all independent across elems.
// Then sum_d wh*tanh = Wsum - 2*S.
__device__ __forceinline__ float z_row_exp(const float* __restrict__ r,
                                           const float4 eg[4], const float4 wh[4])
{
    float acc = 0.f;
    #pragma unroll
    for (int j = 0; j < 4; j++) {
        float4 ev = *reinterpret_cast<const float4*>(&r[j * 128]);
        acc = fmaf(wh[j].x, rcpa(fmaf(ev.x, eg[j].x, 1.0f)), acc);
        acc = fmaf(wh[j].y, rcpa(fmaf(ev.y, eg[j].y, 1.0f)), acc);
        acc = fmaf(wh[j].z, rcpa(fmaf(ev.z, eg[j].z, 1.0f)), acc);
        acc = fmaf(wh[j].w, rcpa(fmaf(ev.w, eg[j].w, 1.0f)), acc);
    }
    return acc;
}

// ---------------------------------------------------------------------------
// Fused kernel, one CTA per (b,t): grid = B*T = 4096, 128 threads (4 warps).
// Warps split k (stride-4, 13/12/12/12). Warp 3 adds z_ext; warp 0 softmax.
// ---------------------------------------------------------------------------
__global__ __launch_bounds__(128, 8)
void fused_attn_kernel(const float* __restrict__ V, const float* __restrict__ s_t,
                       const float* __restrict__ Wh, const float* __restrict__ bh,
                       float* __restrict__ out)
{
    __shared__ __align__(16) float part[4][512];
    __shared__ float z_s[52];
    __shared__ float alpha_s[52];
    __shared__ float beta_sh;

    const int tid  = threadIdx.x;
    const int lane = tid & 31;
    const int w    = tid >> 5;
    const int bt = blockIdx.x;
    const int b  = bt >> 8;            // bt / T_

    // eg = exp(2*cg) row and Wh: register-resident. d = 128j + 4*lane + c.
    float4 eg[4], wh[4];
    float wsum;
    {
        const float* __restrict__ cgrow = g_cg + (size_t)bt * 512 + lane * 4;
        const float* __restrict__ whrow = Wh + lane * 4;
        float s = 0.f;
        #pragma unroll
        for (int j = 0; j < 4; j++) {
            eg[j] = *reinterpret_cast<const float4*>(&cgrow[j * 128]);
            wh[j] = *reinterpret_cast<const float4*>(&whrow[j * 128]);
            s += (wh[j].x + wh[j].y) + (wh[j].z + wh[j].w);
        }
        // full-warp Wsum (same value in all lanes)
        #pragma unroll
        for (int o = 16; o > 0; o >>= 1)
            s += __shfl_xor_sync(0xffffffffu, s, o);
        wsum = s;
    }
    const float bhv = bh[0];

    const float* __restrict__ cvb = g_cv + (size_t)b * (K_ * 512) + lane * 4;

    // ---- z over this warp's k-subset: k = w, w+4, w+8, ... ----
    const int n = (K_ - w + 3) >> 2;   // 13,12,12,12
    int i = 0;
    for (; i + 1 < n; i += 2) {
        const int k0 = w + 4 * i;
        const int k1 = k0 + 4;
        float S0 = z_row_exp(cvb + (size_t)k0 * 512, eg, wh);
        float S1 = z_row_exp(cvb + (size_t)k1 * 512, eg, wh);
        #pragma unroll
        for (int o = 16; o > 0; o >>= 1) {
            S0 += __shfl_xor_sync(0xffffffffu, S0, o);
            S1 += __shfl_xor_sync(0xffffffffu, S1, o);
        }
        if (lane == 0) {
            z_s[k0] = fmaf(-2.0f, S0, wsum) + bhv;
            z_s[k1] = fmaf(-2.0f, S1, wsum) + bhv;
        }
    }
    if (i < n) {
        const int k0 = w + 4 * i;
        float S0 = z_row_exp(cvb + (size_t)k0 * 512, eg, wh);
        #pragma unroll
        for (int o = 16; o > 0; o >>= 1)
            S0 += __shfl_xor_sync(0xffffffffu, S0, o);
        if (lane == 0) z_s[k0] = fmaf(-2.0f, S0, wsum) + bhv;
    }

    // ---- z_ext (warp 3): exp(2*cs) row x eg ----
    if (w == 3) {
        float S = z_row_exp(g_cs + (size_t)bt * 512 + lane * 4, eg, wh);
        #pragma unroll
        for (int o = 16; o > 0; o >>= 1)
            S += __shfl_xor_sync(0xffffffffu, S, o);
        if (lane == 0) z_s[K_] = fmaf(-2.0f, S, wsum) + bhv;
    }
    __syncthreads();

    // ---- softmaxes (warp 0): alpha over 49, beta from extended 50 ----
    if (w == 0) {
        float z0 = (lane < K_)      ? z_s[lane]      : -1e30f;
        float z1 = (lane + 32 < K_) ? z_s[lane + 32] : -1e30f;
        float ze = z_s[K_];
        float m = fmaxf(fmaxf(z0, z1), ze);
        #pragma unroll
        for (int o = 16; o > 0; o >>= 1)
            m = fmaxf(m, __shfl_xor_sync(0xffffffffu, m, o));

        float e0 = (lane < K_)      ? __expf(z0 - m) : 0.f;
        float e1 = (lane + 32 < K_) ? __expf(z1 - m) : 0.f;
        float ee = __expf(ze - m);

        float s = e0 + e1;
        #pragma unroll
        for (int o = 16; o > 0; o >>= 1)
            s += __shfl_xor_sync(0xffffffffu, s, o);
        const float beta = ee / (s + ee);
        const float inv = 1.0f / s;

        if (lane < K_) {
            float a0 = e0 * inv;
            alpha_s[lane] = a0;
            out[OUT_ALPHA + (size_t)bt * K_ + lane] = a0;
        }
        if (lane + 32 < K_) {
            float a1 = e1 * inv;
            alpha_s[lane + 32] = a1;
            out[OUT_ALPHA + (size_t)bt * K_ + lane + 32] = a1;
        }
        if (lane == 0) {
            beta_sh = beta;
            out[OUT_BETA + bt] = beta;
        }
    }
    __syncthreads();

    // ---- c_t partial over this warp's k-subset ----
    float4 cacc[4];
    #pragma unroll
    for (int j = 0; j < 4; j++) cacc[j] = make_float4(0.f, 0.f, 0.f, 0.f);

    const float* __restrict__ Vb = V + (size_t)b * (K_ * 512) + lane * 4;
    i = 0;
    for (; i + 1 < n; i += 2) {
        const int k0 = w + 4 * i;
        const int k1 = k0 + 4;
        const float a0 = alpha_s[k0];
        const float a1 = alpha_s[k1];
        const float* __restrict__ r0 = Vb + (size_t)k0 * 512;
        const float* __restrict__ r1 = Vb + (size_t)k1 * 512;
        #pragma unroll
        for (int j = 0; j < 4; j++) {
            float4 va = *reinterpret_cast<const float4*>(&r0[j * 128]);
            float4 vb = *reinterpret_cast<const float4*>(&r1[j * 128]);
            cacc[j].x = fmaf(a0, va.x, fmaf(a1, vb.x, cacc[j].x));
            cacc[j].y = fmaf(a0, va.y, fmaf(a1, vb.y, cacc[j].y));
            cacc[j].z = fmaf(a0, va.z, fmaf(a1, vb.z, cacc[j].z));
            cacc[j].w = fmaf(a0, va.w, fmaf(a1, vb.w, cacc[j].w));
        }
    }
    if (i < n) {
        const int k0 = w + 4 * i;
        const float a0 = alpha_s[k0];
        const float* __restrict__ r0 = Vb + (size_t)k0 * 512;
        #pragma unroll
        for (int j = 0; j < 4; j++) {
            float4 va = *reinterpret_cast<const float4*>(&r0[j * 128]);
            cacc[j].x = fmaf(a0, va.x, cacc[j].x);
            cacc[j].y = fmaf(a0, va.y, cacc[j].y);
            cacc[j].z = fmaf(a0, va.z, cacc[j].z);
            cacc[j].w = fmaf(a0, va.w, cacc[j].w);
        }
    }
    #pragma unroll
    for (int j = 0; j < 4; j++)
        *reinterpret_cast<float4*>(&part[w][j * 128 + lane * 4]) = cacc[j];
    __syncthreads();

    // ---- combine partials + blend: thread owns d in [4*tid, 4*tid+4) ----
    {
        const float beta = beta_sh;
        const int d = tid * 4;
        float4 p0 = *reinterpret_cast<const float4*>(&part[0][d]);
        float4 p1 = *reinterpret_cast<const float4*>(&part[1][d]);
        float4 p2 = *reinterpret_cast<const float4*>(&part[2][d]);
        float4 p3 = *reinterpret_cast<const float4*>(&part[3][d]);
        float4 c;
        c.x = (p0.x + p1.x) + (p2.x + p3.x);
        c.y = (p0.y + p1.y) + (p2.y + p3.y);
        c.z = (p0.z + p1.z) + (p2.z + p3.z);
        c.w = (p0.w + p1.w) + (p2.w + p3.w);
        float4 sv = *reinterpret_cast<const float4*>(&s_t[(size_t)bt * 512 + d]);
        float4 o;
        o.x = fmaf(beta, sv.x - c.x, c.x);
        o.y = fmaf(beta, sv.y - c.y, c.y);
        o.z = fmaf(beta, sv.z - c.z, c.z);
        o.w = fmaf(beta, sv.w - c.w, c.w);
        *reinterpret_cast<float4*>(&out[(size_t)bt * 512 + d]) = o;
    }
}

// ---------------------------------------------------------------------------
extern "C" void kernel_launch(void* const* d_in, const int* in_sizes, int n_in,
                              void* d_out, int out_size)
{
    (void)in_sizes; (void)n_in; (void)out_size;
    const float* V   = (const float*)d_in[0];
    const float* h_t = (const float*)d_in[1];
    const float* s_t = (const float*)d_in[2];
    const float* Wv  = (const float*)d_in[3];
    const float* bv  = (const float*)d_in[4];
    const float* Wg  = (const float*)d_in[5];
    const float* bg  = (const float*)d_in[6];
    const float* Ws  = (const float*)d_in[7];
    const float* bs  = (const float*)d_in[8];
    const float* Wh  = (const float*)d_in[9];
    const float* bh  = (const float*)d_in[10];
    float* out = (float*)d_out;

    gemm3_tf32_kernel<<<dim3(4, 71), 256>>>(V, h_t, s_t, Wv, bv, Wg, bg, Ws, bs);
    fused_attn_kernel<<<dim3(B_ * T_), 128>>>(V, s_t, Wh, bh, out);
}

// round 14
// speedup vs baseline: 1.8707x; 1.8707x over previous
#include <cuda_runtime.h>
#include <cuda_fp16.h>
#include <cstdint>

// Problem constants
#define B_ 16
#define K_ 49
#define T_ 256
#define H_ 512
#define D_ 512

// Output packing: (c_hat_t, alpha_t, beta_t) flattened in order
#define OUT_ALPHA (B_ * T_ * H_)              // 2097152
#define OUT_BETA  (OUT_ALPHA + B_ * T_ * K_)  // 2297856

// Scratch: cv and cs stored as fp16 (packed pairs) -> TANH.H2 + half the LDG
// bytes in the fused z-loop. cg stays f32 (read once per CTA into registers).
__device__ __half g_cv[B_ * K_ * D_];   // half(V @ Wv + bv)
__device__ float  g_cg[B_ * T_ * D_];   // h_t @ Wg + bg
__device__ __half g_cs[B_ * T_ * D_];   // half(s_t @ Ws + bs)

// pack two f32 -> f16x2 (lo = first arg, hi = second arg)
__device__ __forceinline__ uint32_t pack_h2(float lo, float hi)
{ uint32_t d; asm("cvt.rn.f16x2.f32 %0, %1, %2;" : "=r"(d) : "f"(hi), "f"(lo)); return d; }

__device__ __forceinline__ uint32_t hadd2(uint32_t a, uint32_t b)
{ uint32_t d; asm("add.rn.f16x2 %0, %1, %2;" : "=r"(d) : "r"(a), "r"(b)); return d; }

__device__ __forceinline__ uint32_t tanh_h2(uint32_t a)
{ uint32_t d; asm("tanh.approx.f16x2 %0, %1;" : "=r"(d) : "r"(a)); return d; }

__device__ __forceinline__ float2 h2_to_f2(uint32_t t)
{
    float f0, f1;
    asm("{\n\t.reg .f16 l, h;\n\tmov.b32 {l, h}, %2;\n\t"
        "cvt.f32.f16 %0, l;\n\tcvt.f32.f16 %1, h;\n\t}"
        : "=f"(f0), "=f"(f1) : "r"(t));
    return make_float2(f0, f1);   // f0 = low (even elem), f1 = high (odd elem)
}

// ---------------------------------------------------------------------------
// Merged TF32 mma.sync GEMM: all three C[M,512] = A[M,512]@W + bias.
// cv/cs epilogues store packed fp16 pairs; cg stores f32.
// ---------------------------------------------------------------------------
__global__ __launch_bounds__(256)
void gemm3_tf32_kernel(const float* __restrict__ V, const float* __restrict__ h_t,
                       const float* __restrict__ s_t,
                       const float* __restrict__ Wv, const float* __restrict__ bv,
                       const float* __restrict__ Wg, const float* __restrict__ bg,
                       const float* __restrict__ Wss, const float* __restrict__ bss)
{
    __shared__ float As[128 * 32];     // [m][k], k index xor-swizzled by 4*(m&7)
    __shared__ float Bs[32 * 136];     // [k][n], row stride 136 (pad 8)

    const int nt = blockIdx.x;         // 0..3
    int mt = blockIdx.y;               // 0..70
    const float *A, *W, *bias;
    float* Cf = nullptr;
    __half* Ch = nullptr;
    int M;
    if (mt < 7)       { A = V;   W = Wv;  bias = bv;  Ch = g_cv; M = B_ * K_; }
    else if (mt < 39) { A = h_t; W = Wg;  bias = bg;  Cf = g_cg; M = B_ * T_; mt -= 7; }
    else              { A = s_t; W = Wss; bias = bss; Ch = g_cs; M = B_ * T_; mt -= 39; }

    const int tid  = threadIdx.x;
    const int lane = tid & 31;
    const int wid  = tid >> 5;
    const int g    = lane >> 2;
    const int tg   = lane & 3;
    const int warp_m = (wid >> 2) * 64;
    const int warp_n = (wid & 3) * 32;

    const int mbase = mt * 128;
    const int nbase = nt * 128;

    float acc[4][4][4];
    #pragma unroll
    for (int i = 0; i < 4; i++)
        #pragma unroll
        for (int j = 0; j < 4; j++)
            #pragma unroll
            for (int q = 0; q < 4; q++) acc[i][j][q] = 0.f;

    const int a_m0 = tid >> 3;
    const int a_k4 = (tid & 7) * 4;
    const int w_k0 = tid >> 5;
    const int w_n4 = (tid & 31) * 4;

    float4 pa[4], pw[4];

    #pragma unroll
    for (int i = 0; i < 4; i++) {
        const int row = mbase + a_m0 + i * 32;
        pa[i] = (row < M) ? *reinterpret_cast<const float4*>(&A[(size_t)row * 512 + a_k4])
                          : make_float4(0.f, 0.f, 0.f, 0.f);
        pw[i] = *reinterpret_cast<const float4*>(&W[(size_t)(w_k0 + i * 8) * 512 + nbase + w_n4]);
    }
    #pragma unroll
    for (int i = 0; i < 4; i++) {
        const int m = a_m0 + i * 32;
        *reinterpret_cast<float4*>(&As[m * 32 + (a_k4 ^ (4 * (m & 7)))]) = pa[i];
        *reinterpret_cast<float4*>(&Bs[(w_k0 + i * 8) * 136 + w_n4]) = pw[i];
    }
    __syncthreads();

    const int sw = 4 * g;

    for (int kt = 0; kt < 512; kt += 32) {
        if (kt + 32 < 512) {
            #pragma unroll
            for (int i = 0; i < 4; i++) {
                const int row = mbase + a_m0 + i * 32;
                pa[i] = (row < M) ? *reinterpret_cast<const float4*>(&A[(size_t)row * 512 + kt + 32 + a_k4])
                                  : make_float4(0.f, 0.f, 0.f, 0.f);
                pw[i] = *reinterpret_cast<const float4*>(&W[(size_t)(kt + 32 + w_k0 + i * 8) * 512 + nbase + w_n4]);
            }
        }

        #pragma unroll
        for (int kb = 0; kb < 32; kb += 8) {
            uint32_t af[4][4], bf[4][2];
            #pragma unroll
            for (int mi = 0; mi < 4; mi++) {
                const int m0 = warp_m + mi * 16;
                const int k0 = (kb + tg) ^ sw;
                const int k1 = (kb + tg + 4) ^ sw;
                af[mi][0] = __float_as_uint(As[(m0 + g)     * 32 + k0]);
                af[mi][1] = __float_as_uint(As[(m0 + g + 8) * 32 + k0]);
                af[mi][2] = __float_as_uint(As[(m0 + g)     * 32 + k1]);
                af[mi][3] = __float_as_uint(As[(m0 + g + 8) * 32 + k1]);
            }
            #pragma unroll
            for (int ni = 0; ni < 4; ni++) {
                const int n_ = warp_n + ni * 8 + g;
                bf[ni][0] = __float_as_uint(Bs[(kb + tg)     * 136 + n_]);
                bf[ni][1] = __float_as_uint(Bs[(kb + tg + 4) * 136 + n_]);
            }
            #pragma unroll
            for (int mi = 0; mi < 4; mi++)
                #pragma unroll
                for (int ni = 0; ni < 4; ni++) {
                    asm volatile(
                        "mma.sync.aligned.m16n8k8.row.col.f32.tf32.tf32.f32 "
                        "{%0,%1,%2,%3}, {%4,%5,%6,%7}, {%8,%9}, {%0,%1,%2,%3};"
                        : "+f"(acc[mi][ni][0]), "+f"(acc[mi][ni][1]),
                          "+f"(acc[mi][ni][2]), "+f"(acc[mi][ni][3])
                        : "r"(af[mi][0]), "r"(af[mi][1]), "r"(af[mi][2]), "r"(af[mi][3]),
                          "r"(bf[ni][0]), "r"(bf[ni][1]));
                }
        }
        __syncthreads();
        if (kt + 32 < 512) {
            #pragma unroll
            for (int i = 0; i < 4; i++) {
                const int m = a_m0 + i * 32;
                *reinterpret_cast<float4*>(&As[m * 32 + (a_k4 ^ (4 * (m & 7)))]) = pa[i];
                *reinterpret_cast<float4*>(&Bs[(w_k0 + i * 8) * 136 + w_n4]) = pw[i];
            }
            __syncthreads();
        }
    }

    // Epilogue: bias, then store (f32 for cg; packed fp16 pairs for cv/cs).
    #pragma unroll
    for (int mi = 0; mi < 4; mi++) {
        const int r0 = mbase + warp_m + mi * 16 + g;
        const int r1 = r0 + 8;
        #pragma unroll
        for (int ni = 0; ni < 4; ni++) {
            const int c = nbase + warp_n + ni * 8 + tg * 2;   // even
            const float2 bv2 = *reinterpret_cast<const float2*>(&bias[c]);
            const float o00 = acc[mi][ni][0] + bv2.x, o01 = acc[mi][ni][1] + bv2.y;
            const float o10 = acc[mi][ni][2] + bv2.x, o11 = acc[mi][ni][3] + bv2.y;
            if (Cf) {
                if (r0 < M)
                    *reinterpret_cast<float2*>(&Cf[(size_t)r0 * 512 + c]) = make_float2(o00, o01);
                if (r1 < M)
                    *reinterpret_cast<float2*>(&Cf[(size_t)r1 * 512 + c]) = make_float2(o10, o11);
            } else {
                if (r0 < M)
                    *reinterpret_cast<uint32_t*>(&Ch[(size_t)r0 * 512 + c]) = pack_h2(o00, o01);
                if (r1 < M)
                    *reinterpret_cast<uint32_t*>(&Ch[(size_t)r1 * 512 + c]) = pack_h2(o10, o11);
            }
        }
    }
}

// z-row lane partial over d = 256j + 8*lane + c (c=0..7), fp16x2 pipeline:
// HADD2 -> TANH.H2 -> unpack -> FFMA. 8 TANH.H2 per 16 elems (vs 16 TANH.F32).
__device__ __forceinline__ float z_row_h2(const __half* __restrict__ r,
                                          const uint32_t cgh[8], const float whr[16])
{
    float acc = 0.f;
    #pragma unroll
    for (int j = 0; j < 2; j++) {
        const uint4 v = *reinterpret_cast<const uint4*>(r + j * 256);
        uint32_t t0 = tanh_h2(hadd2(v.x, cgh[4 * j + 0]));
        uint32_t t1 = tanh_h2(hadd2(v.y, cgh[4 * j + 1]));
        uint32_t t2 = tanh_h2(hadd2(v.z, cgh[4 * j + 2]));
        uint32_t t3 = tanh_h2(hadd2(v.w, cgh[4 * j + 3]));
        float2 f0 = h2_to_f2(t0);
        float2 f1 = h2_to_f2(t1);
        float2 f2 = h2_to_f2(t2);
        float2 f3 = h2_to_f2(t3);
        acc = fmaf(f0.x, whr[8 * j + 0], acc);
        acc = fmaf(f0.y, whr[8 * j + 1], acc);
        acc = fmaf(f1.x, whr[8 * j + 2], acc);
        acc = fmaf(f1.y, whr[8 * j + 3], acc);
        acc = fmaf(f2.x, whr[8 * j + 4], acc);
        acc = fmaf(f2.y, whr[8 * j + 5], acc);
        acc = fmaf(f3.x, whr[8 * j + 6], acc);
        acc = fmaf(f3.y, whr[8 * j + 7], acc);
    }
    return acc;
}

// ---------------------------------------------------------------------------
// Fused kernel, one CTA per (b,t): grid = B*T = 4096, 128 threads (4 warps).
// Warps split k (stride-4, 13/12/12/12). Warp 3 adds z_ext; warp 0 softmax.
// ---------------------------------------------------------------------------
__global__ __launch_bounds__(128, 8)
void fused_attn_kernel(const float* __restrict__ V, const float* __restrict__ s_t,
                       const float* __restrict__ Wh, const float* __restrict__ bh,
                       float* __restrict__ out)
{
    __shared__ __align__(16) float part[4][512];
    __shared__ float z_s[52];
    __shared__ float alpha_s[52];
    __shared__ float beta_sh;

    const int tid  = threadIdx.x;
    const int lane = tid & 31;
    const int w    = tid >> 5;
    const int bt = blockIdx.x;
    const int b  = bt >> 8;            // bt / T_

    // z-path registers: cg packed to h2 (d = 256j + 8*lane + c), Wh as f32.
    uint32_t cgh[8];
    float whr[16];
    {
        const float* __restrict__ cgrow = g_cg + (size_t)bt * 512 + lane * 8;
        const float* __restrict__ whrow = Wh + lane * 8;
        #pragma unroll
        for (int j = 0; j < 2; j++) {
            float4 a0 = *reinterpret_cast<const float4*>(&cgrow[j * 256]);
            float4 a1 = *reinterpret_cast<const float4*>(&cgrow[j * 256 + 4]);
            cgh[4 * j + 0] = pack_h2(a0.x, a0.y);
            cgh[4 * j + 1] = pack_h2(a0.z, a0.w);
            cgh[4 * j + 2] = pack_h2(a1.x, a1.y);
            cgh[4 * j + 3] = pack_h2(a1.z, a1.w);
            float4 w0 = *reinterpret_cast<const float4*>(&whrow[j * 256]);
            float4 w1 = *reinterpret_cast<const float4*>(&whrow[j * 256 + 4]);
            whr[8 * j + 0] = w0.x; whr[8 * j + 1] = w0.y;
            whr[8 * j + 2] = w0.z; whr[8 * j + 3] = w0.w;
            whr[8 * j + 4] = w1.x; whr[8 * j + 5] = w1.y;
            whr[8 * j + 6] = w1.z; whr[8 * j + 7] = w1.w;
        }
    }
    const float bhv = bh[0];

    const __half* __restrict__ cvb = g_cv + (size_t)b * (K_ * 512) + lane * 8;

    // ---- z over this warp's k-subset: k = w, w+4, w+8, ... ----
    const int n = (K_ - w + 3) >> 2;   // 13,12,12,12
    int i = 0;
    for (; i + 1 < n; i += 2) {
        const int k0 = w + 4 * i;
        const int k1 = k0 + 4;
        float a0 = z_row_h2(cvb + (size_t)k0 * 512, cgh, whr);
        float a1 = z_row_h2(cvb + (size_t)k1 * 512, cgh, whr);
        #pragma unroll
        for (int o = 16; o > 0; o >>= 1) {
            a0 += __shfl_xor_sync(0xffffffffu, a0, o);
            a1 += __shfl_xor_sync(0xffffffffu, a1, o);
        }
        if (lane == 0) { z_s[k0] = a0 + bhv; z_s[k1] = a1 + bhv; }
    }
    if (i < n) {
        const int k0 = w + 4 * i;
        float a0 = z_row_h2(cvb + (size_t)k0 * 512, cgh, whr);
        #pragma unroll
        for (int o = 16; o > 0; o >>= 1)
            a0 += __shfl_xor_sync(0xffffffffu, a0, o);
        if (lane == 0) z_s[k0] = a0 + bhv;
    }

    // ---- z_ext (warp 3): content_s = cs + cg ----
    if (w == 3) {
        float acc = z_row_h2(g_cs + (size_t)bt * 512 + lane * 8, cgh, whr);
        #pragma unroll
        for (int o = 16; o > 0; o >>= 1)
            acc += __shfl_xor_sync(0xffffffffu, acc, o);
        if (lane == 0) z_s[K_] = acc + bhv;
    }
    __syncthreads();

    // ---- softmaxes (warp 0): alpha over 49, beta from extended 50 ----
    if (w == 0) {
        float z0 = (lane < K_)      ? z_s[lane]      : -1e30f;
        float z1 = (lane + 32 < K_) ? z_s[lane + 32] : -1e30f;
        float ze = z_s[K_];
        float m = fmaxf(fmaxf(z0, z1), ze);
        #pragma unroll
        for (int o = 16; o > 0; o >>= 1)
            m = fmaxf(m, __shfl_xor_sync(0xffffffffu, m, o));

        float e0 = (lane < K_)      ? __expf(z0 - m) : 0.f;
        float e1 = (lane + 32 < K_) ? __expf(z1 - m) : 0.f;
        float ee = __expf(ze - m);

        float s = e0 + e1;
        #pragma unroll
        for (int o = 16; o > 0; o >>= 1)
            s += __shfl_xor_sync(0xffffffffu, s, o);
        const float beta = ee / (s + ee);
        const float inv = 1.0f / s;

        if (lane < K_) {
            float a0 = e0 * inv;
            alpha_s[lane] = a0;
            out[OUT_ALPHA + (size_t)bt * K_ + lane] = a0;
        }
        if (lane + 32 < K_) {
            float a1 = e1 * inv;
            alpha_s[lane + 32] = a1;
            out[OUT_ALPHA + (size_t)bt * K_ + lane + 32] = a1;
        }
        if (lane == 0) {
            beta_sh = beta;
            out[OUT_BETA + bt] = beta;
        }
    }
    __syncthreads();

    // ---- c_t partial over this warp's k-subset (f32, V input) ----
    float4 cacc[4];
    #pragma unroll
    for (int j = 0; j < 4; j++) cacc[j] = make_float4(0.f, 0.f, 0.f, 0.f);

    const float* __restrict__ Vb = V + (size_t)b * (K_ * 512) + lane * 4;
    i = 0;
    for (; i + 1 < n; i += 2) {
        const int k0 = w + 4 * i;
        const int k1 = k0 + 4;
        const float a0 = alpha_s[k0];
        const float a1 = alpha_s[k1];
        const float* __restrict__ r0 = Vb + (size_t)k0 * 512;
        const float* __restrict__ r1 = Vb + (size_t)k1 * 512;
        #pragma unroll
        for (int j = 0; j < 4; j++) {
            float4 va = *reinterpret_cast<const float4*>(&r0[j * 128]);
            float4 vb = *reinterpret_cast<const float4*>(&r1[j * 128]);
            cacc[j].x = fmaf(a0, va.x, fmaf(a1, vb.x, cacc[j].x));
            cacc[j].y = fmaf(a0, va.y, fmaf(a1, vb.y, cacc[j].y));
            cacc[j].z = fmaf(a0, va.z, fmaf(a1, vb.z, cacc[j].z));
            cacc[j].w = fmaf(a0, va.w, fmaf(a1, vb.w, cacc[j].w));
        }
    }
    if (i < n) {
        const int k0 = w + 4 * i;
        const float a0 = alpha_s[k0];
        const float* __restrict__ r0 = Vb + (size_t)k0 * 512;
        #pragma unroll
        for (int j = 0; j < 4; j++) {
            float4 va = *reinterpret_cast<const float4*>(&r0[j * 128]);
            cacc[j].x = fmaf(a0, va.x, cacc[j].x);
            cacc[j].y = fmaf(a0, va.y, cacc[j].y);
            cacc[j].z = fmaf(a0, va.z, cacc[j].z);
            cacc[j].w = fmaf(a0, va.w, cacc[j].w);
        }
    }
    #pragma unroll
    for (int j = 0; j < 4; j++)
        *reinterpret_cast<float4*>(&part[w][j * 128 + lane * 4]) = cacc[j];
    __syncthreads();

    // ---- combine partials + blend: thread owns d in [4*tid, 4*tid+4) ----
    {
        const float beta = beta_sh;
        const int d = tid * 4;
        float4 p0 = *reinterpret_cast<const float4*>(&part[0][d]);
        float4 p1 = *reinterpret_cast<const float4*>(&part[1][d]);
        float4 p2 = *reinterpret_cast<const float4*>(&part[2][d]);
        float4 p3 = *reinterpret_cast<const float4*>(&part[3][d]);
        float4 c;
        c.x = (p0.x + p1.x) + (p2.x + p3.x);
        c.y = (p0.y + p1.y) + (p2.y + p3.y);
        c.z = (p0.z + p1.z) + (p2.z + p3.z);
        c.w = (p0.w + p1.w) + (p2.w + p3.w);
        float4 sv = *reinterpret_cast<const float4*>(&s_t[(size_t)bt * 512 + d]);
        float4 o;
        o.x = fmaf(beta, sv.x - c.x, c.x);
        o.y = fmaf(beta, sv.y - c.y, c.y);
        o.z = fmaf(beta, sv.z - c.z, c.z);
        o.w = fmaf(beta, sv.w - c.w, c.w);
        *reinterpret_cast<float4*>(&out[(size_t)bt * 512 + d]) = o;
    }
}

// ---------------------------------------------------------------------------
extern "C" void kernel_launch(void* const* d_in, const int* in_sizes, int n_in,
                              void* d_out, int out_size)
{
    (void)in_sizes; (void)n_in; (void)out_size;
    const float* V   = (const float*)d_in[0];
    const float* h_t = (const float*)d_in[1];
    const float* s_t = (const float*)d_in[2];
    const float* Wv  = (const float*)d_in[3];
    const float* bv  = (const float*)d_in[4];
    const float* Wg  = (const float*)d_in[5];
    const float* bg  = (const float*)d_in[6];
    const float* Ws  = (const float*)d_in[7];
    const float* bs  = (const float*)d_in[8];
    const float* Wh  = (const float*)d_in[9];
    const float* bh  = (const float*)d_in[10];
    float* out = (float*)d_out;

    gemm3_tf32_kernel<<<dim3(4, 71), 256>>>(V, h_t, s_t, Wv, bv, Wg, bg, Ws, bs);
    fused_attn_kernel<<<dim3(B_ * T_), 128>>>(V, s_t, Wh, bh, out);
}

// round 16
// speedup vs baseline: 1.9088x; 1.0204x over previous
#include <cuda_runtime.h>
#include <cuda_fp16.h>
#include <cstdint>

// Problem constants
#define B_ 16
#define K_ 49
#define T_ 256
#define H_ 512
#define D_ 512

// Output packing: (c_hat_t, alpha_t, beta_t) flattened in order
#define OUT_ALPHA (B_ * T_ * H_)              // 2097152
#define OUT_BETA  (OUT_ALPHA + B_ * T_ * K_)  // 2297856

// Scratch: cv and cs stored as fp16 (packed pairs) -> TANH.H2 + half the LDG
// bytes in the fused z-loop. cg stays f32 (read once per CTA into registers).
__device__ __half g_cv[B_ * K_ * D_];   // half(V @ Wv + bv)
__device__ float  g_cg[B_ * T_ * D_];   // h_t @ Wg + bg
__device__ __half g_cs[B_ * T_ * D_];   // half(s_t @ Ws + bs)

// pack two f32 -> f16x2 (lo = first arg, hi = second arg)
__device__ __forceinline__ uint32_t pack_h2(float lo, float hi)
{ uint32_t d; asm("cvt.rn.f16x2.f32 %0, %1, %2;" : "=r"(d) : "f"(hi), "f"(lo)); return d; }

__device__ __forceinline__ uint32_t hadd2(uint32_t a, uint32_t b)
{ uint32_t d; asm("add.rn.f16x2 %0, %1, %2;" : "=r"(d) : "r"(a), "r"(b)); return d; }

__device__ __forceinline__ uint32_t tanh_h2(uint32_t a)
{ uint32_t d; asm("tanh.approx.f16x2 %0, %1;" : "=r"(d) : "r"(a)); return d; }

__device__ __forceinline__ float2 h2_to_f2(uint32_t t)
{
    float f0, f1;
    asm("{\n\t.reg .f16 l, h;\n\tmov.b32 {l, h}, %2;\n\t"
        "cvt.f32.f16 %0, l;\n\tcvt.f32.f16 %1, h;\n\t}"
        : "=f"(f0), "=f"(f1) : "r"(t));
    return make_float2(f0, f1);
}

// ---------------------------------------------------------------------------
// Merged TF32 mma.sync GEMM: all three C[M,512] = A[M,512]@W + bias.
// cv/cs epilogues store packed fp16 pairs; cg stores f32.
// ---------------------------------------------------------------------------
__global__ __launch_bounds__(256)
void gemm3_tf32_kernel(const float* __restrict__ V, const float* __restrict__ h_t,
                       const float* __restrict__ s_t,
                       const float* __restrict__ Wv, const float* __restrict__ bv,
                       const float* __restrict__ Wg, const float* __restrict__ bg,
                       const float* __restrict__ Wss, const float* __restrict__ bss)
{
    __shared__ float As[128 * 32];     // [m][k], k index xor-swizzled by 4*(m&7)
    __shared__ float Bs[32 * 136];     // [k][n], row stride 136 (pad 8)

    const int nt = blockIdx.x;         // 0..3
    int mt = blockIdx.y;               // 0..70
    const float *A, *W, *bias;
    float* Cf = nullptr;
    __half* Ch = nullptr;
    int M;
    if (mt < 7)       { A = V;   W = Wv;  bias = bv;  Ch = g_cv; M = B_ * K_; }
    else if (mt < 39) { A = h_t; W = Wg;  bias = bg;  Cf = g_cg; M = B_ * T_; mt -= 7; }
    else              { A = s_t; W = Wss; bias = bss; Ch = g_cs; M = B_ * T_; mt -= 39; }

    const int tid  = threadIdx.x;
    const int lane = tid & 31;
    const int wid  = tid >> 5;
    const int g    = lane >> 2;
    const int tg   = lane & 3;
    const int warp_m = (wid >> 2) * 64;
    const int warp_n = (wid & 3) * 32;

    const int mbase = mt * 128;
    const int nbase = nt * 128;

    float acc[4][4][4];
    #pragma unroll
    for (int i = 0; i < 4; i++)
        #pragma unroll
        for (int j = 0; j < 4; j++)
            #pragma unroll
            for (int q = 0; q < 4; q++) acc[i][j][q] = 0.f;

    const int a_m0 = tid >> 3;
    const int a_k4 = (tid & 7) * 4;
    const int w_k0 = tid >> 5;
    const int w_n4 = (tid & 31) * 4;

    float4 pa[4], pw[4];

    #pragma unroll
    for (int i = 0; i < 4; i++) {
        const int row = mbase + a_m0 + i * 32;
        pa[i] = (row < M) ? *reinterpret_cast<const float4*>(&A[(size_t)row * 512 + a_k4])
                          : make_float4(0.f, 0.f, 0.f, 0.f);
        pw[i] = *reinterpret_cast<const float4*>(&W[(size_t)(w_k0 + i * 8) * 512 + nbase + w_n4]);
    }
    #pragma unroll
    for (int i = 0; i < 4; i++) {
        const int m = a_m0 + i * 32;
        *reinterpret_cast<float4*>(&As[m * 32 + (a_k4 ^ (4 * (m & 7)))]) = pa[i];
        *reinterpret_cast<float4*>(&Bs[(w_k0 + i * 8) * 136 + w_n4]) = pw[i];
    }
    __syncthreads();

    const int sw = 4 * g;

    for (int kt = 0; kt < 512; kt += 32) {
        if (kt + 32 < 512) {
            #pragma unroll
            for (int i = 0; i < 4; i++) {
                const int row = mbase + a_m0 + i * 32;
                pa[i] = (row < M) ? *reinterpret_cast<const float4*>(&A[(size_t)row * 512 + kt + 32 + a_k4])
                                  : make_float4(0.f, 0.f, 0.f, 0.f);
                pw[i] = *reinterpret_cast<const float4*>(&W[(size_t)(kt + 32 + w_k0 + i * 8) * 512 + nbase + w_n4]);
            }
        }

        #pragma unroll
        for (int kb = 0; kb < 32; kb += 8) {
            uint32_t af[4][4], bf[4][2];
            #pragma unroll
            for (int mi = 0; mi < 4; mi++) {
                const int m0 = warp_m + mi * 16;
                const int k0 = (kb + tg) ^ sw;
                const int k1 = (kb + tg + 4) ^ sw;
                af[mi][0] = __float_as_uint(As[(m0 + g)     * 32 + k0]);
                af[mi][1] = __float_as_uint(As[(m0 + g + 8) * 32 + k0]);
                af[mi][2] = __float_as_uint(As[(m0 + g)     * 32 + k1]);
                af[mi][3] = __float_as_uint(As[(m0 + g + 8) * 32 + k1]);
            }
            #pragma unroll
            for (int ni = 0; ni < 4; ni++) {
                const int n_ = warp_n + ni * 8 + g;
                bf[ni][0] = __float_as_uint(Bs[(kb + tg)     * 136 + n_]);
                bf[ni][1] = __float_as_uint(Bs[(kb + tg + 4) * 136 + n_]);
            }
            #pragma unroll
            for (int mi = 0; mi < 4; mi++)
                #pragma unroll
                for (int ni = 0; ni < 4; ni++) {
                    asm volatile(
                        "mma.sync.aligned.m16n8k8.row.col.f32.tf32.tf32.f32 "
                        "{%0,%1,%2,%3}, {%4,%5,%6,%7}, {%8,%9}, {%0,%1,%2,%3};"
                        : "+f"(acc[mi][ni][0]), "+f"(acc[mi][ni][1]),
                          "+f"(acc[mi][ni][2]), "+f"(acc[mi][ni][3])
                        : "r"(af[mi][0]), "r"(af[mi][1]), "r"(af[mi][2]), "r"(af[mi][3]),
                          "r"(bf[ni][0]), "r"(bf[ni][1]));
                }
        }
        __syncthreads();
        if (kt + 32 < 512) {
            #pragma unroll
            for (int i = 0; i < 4; i++) {
                const int m = a_m0 + i * 32;
                *reinterpret_cast<float4*>(&As[m * 32 + (a_k4 ^ (4 * (m & 7)))]) = pa[i];
                *reinterpret_cast<float4*>(&Bs[(w_k0 + i * 8) * 136 + w_n4]) = pw[i];
            }
            __syncthreads();
        }
    }

    // Epilogue: bias, then store (f32 for cg; packed fp16 pairs for cv/cs).
    #pragma unroll
    for (int mi = 0; mi < 4; mi++) {
        const int r0 = mbase + warp_m + mi * 16 + g;
        const int r1 = r0 + 8;
        #pragma unroll
        for (int ni = 0; ni < 4; ni++) {
            const int c = nbase + warp_n + ni * 8 + tg * 2;
            const float2 bv2 = *reinterpret_cast<const float2*>(&bias[c]);
            const float o00 = acc[mi][ni][0] + bv2.x, o01 = acc[mi][ni][1] + bv2.y;
            const float o10 = acc[mi][ni][2] + bv2.x, o11 = acc[mi][ni][3] + bv2.y;
            if (Cf) {
                if (r0 < M)
                    *reinterpret_cast<float2*>(&Cf[(size_t)r0 * 512 + c]) = make_float2(o00, o01);
                if (r1 < M)
                    *reinterpret_cast<float2*>(&Cf[(size_t)r1 * 512 + c]) = make_float2(o10, o11);
            } else {
                if (r0 < M)
                    *reinterpret_cast<uint32_t*>(&Ch[(size_t)r0 * 512 + c]) = pack_h2(o00, o01);
                if (r1 < M)
                    *reinterpret_cast<uint32_t*>(&Ch[(size_t)r1 * 512 + c]) = pack_h2(o10, o11);
            }
        }
    }
}

// z-row lane partial over d = 256j + 8*lane + c (c=0..7), fp16x2 pipeline.
__device__ __forceinline__ float z_row_h2(const __half* __restrict__ r,
                                          const uint32_t cgh[8], const float whr[16])
{
    float acc = 0.f;
    #pragma unroll
    for (int j = 0; j < 2; j++) {
        const uint4 v = *reinterpret_cast<const uint4*>(r + j * 256);
        uint32_t t0 = tanh_h2(hadd2(v.x, cgh[4 * j + 0]));
        uint32_t t1 = tanh_h2(hadd2(v.y, cgh[4 * j + 1]));
        uint32_t t2 = tanh_h2(hadd2(v.z, cgh[4 * j + 2]));
        uint32_t t3 = tanh_h2(hadd2(v.w, cgh[4 * j + 3]));
        float2 f0 = h2_to_f2(t0);
        float2 f1 = h2_to_f2(t1);
        float2 f2 = h2_to_f2(t2);
        float2 f3 = h2_to_f2(t3);
        acc = fmaf(f0.x, whr[8 * j + 0], acc);
        acc = fmaf(f0.y, whr[8 * j + 1], acc);
        acc = fmaf(f1.x, whr[8 * j + 2], acc);
        acc = fmaf(f1.y, whr[8 * j + 3], acc);
        acc = fmaf(f2.x, whr[8 * j + 4], acc);
        acc = fmaf(f2.y, whr[8 * j + 5], acc);
        acc = fmaf(f3.x, whr[8 * j + 6], acc);
        acc = fmaf(f3.y, whr[8 * j + 7], acc);
    }
    return acc;
}

// ---------------------------------------------------------------------------
// Fused z + softmax kernel (NO c_t): one CTA per (b,t), 128 threads (4 warps).
// Warps split k (stride-4). Warp 3 adds z_ext; warp 0 does softmax and writes
// alpha/beta directly to out. c_t is done by ct_gemm_kernel afterwards.
// ---------------------------------------------------------------------------
__global__ __launch_bounds__(128, 8)
void fused_z_kernel(const float* __restrict__ Wh, const float* __restrict__ bh,
                    float* __restrict__ out)
{
    __shared__ float z_s[52];

    const int tid  = threadIdx.x;
    const int lane = tid & 31;
    const int w    = tid >> 5;
    const int bt = blockIdx.x;
    const int b  = bt >> 8;            // bt / T_

    // z-path registers: cg packed to h2 (d = 256j + 8*lane + c), Wh as f32.
    uint32_t cgh[8];
    float whr[16];
    {
        const float* __restrict__ cgrow = g_cg + (size_t)bt * 512 + lane * 8;
        const float* __restrict__ whrow = Wh + lane * 8;
        #pragma unroll
        for (int j = 0; j < 2; j++) {
            float4 a0 = *reinterpret_cast<const float4*>(&cgrow[j * 256]);
            float4 a1 = *reinterpret_cast<const float4*>(&cgrow[j * 256 + 4]);
            cgh[4 * j + 0] = pack_h2(a0.x, a0.y);
            cgh[4 * j + 1] = pack_h2(a0.z, a0.w);
            cgh[4 * j + 2] = pack_h2(a1.x, a1.y);
            cgh[4 * j + 3] = pack_h2(a1.z, a1.w);
            float4 w0 = *reinterpret_cast<const float4*>(&whrow[j * 256]);
            float4 w1 = *reinterpret_cast<const float4*>(&whrow[j * 256 + 4]);
            whr[8 * j + 0] = w0.x; whr[8 * j + 1] = w0.y;
            whr[8 * j + 2] = w0.z; whr[8 * j + 3] = w0.w;
            whr[8 * j + 4] = w1.x; whr[8 * j + 5] = w1.y;
            whr[8 * j + 6] = w1.z; whr[8 * j + 7] = w1.w;
        }
    }
    const float bhv = bh[0];

    const __half* __restrict__ cvb = g_cv + (size_t)b * (K_ * 512) + lane * 8;

    // ---- z over this warp's k-subset: k = w, w+4, w+8, ... ----
    const int n = (K_ - w + 3) >> 2;   // 13,12,12,12
    int i = 0;
    for (; i + 1 < n; i += 2) {
        const int k0 = w + 4 * i;
        const int k1 = k0 + 4;
        float a0 = z_row_h2(cvb + (size_t)k0 * 512, cgh, whr);
        float a1 = z_row_h2(cvb + (size_t)k1 * 512, cgh, whr);
        #pragma unroll
        for (int o = 16; o > 0; o >>= 1) {
            a0 += __shfl_xor_sync(0xffffffffu, a0, o);
            a1 += __shfl_xor_sync(0xffffffffu, a1, o);
        }
        if (lane == 0) { z_s[k0] = a0 + bhv; z_s[k1] = a1 + bhv; }
    }
    if (i < n) {
        const int k0 = w + 4 * i;
        float a0 = z_row_h2(cvb + (size_t)k0 * 512, cgh, whr);
        #pragma unroll
        for (int o = 16; o > 0; o >>= 1)
            a0 += __shfl_xor_sync(0xffffffffu, a0, o);
        if (lane == 0) z_s[k0] = a0 + bhv;
    }

    // ---- z_ext (warp 3): content_s = cs + cg ----
    if (w == 3) {
        float acc = z_row_h2(g_cs + (size_t)bt * 512 + lane * 8, cgh, whr);
        #pragma unroll
        for (int o = 16; o > 0; o >>= 1)
            acc += __shfl_xor_sync(0xffffffffu, acc, o);
        if (lane == 0) z_s[K_] = acc + bhv;
    }
    __syncthreads();

    // ---- softmaxes (warp 0): alpha over 49, beta from extended 50 ----
    if (w == 0) {
        float z0 = (lane < K_)      ? z_s[lane]      : -1e30f;
        float z1 = (lane + 32 < K_) ? z_s[lane + 32] : -1e30f;
        float ze = z_s[K_];
        float m = fmaxf(fmaxf(z0, z1), ze);
        #pragma unroll
        for (int o = 16; o > 0; o >>= 1)
            m = fmaxf(m, __shfl_xor_sync(0xffffffffu, m, o));

        float e0 = (lane < K_)      ? __expf(z0 - m) : 0.f;
        float e1 = (lane + 32 < K_) ? __expf(z1 - m) : 0.f;
        float ee = __expf(ze - m);

        float s = e0 + e1;
        #pragma unroll
        for (int o = 16; o > 0; o >>= 1)
            s += __shfl_xor_sync(0xffffffffu, s, o);
        const float beta = ee / (s + ee);
        const float inv = 1.0f / s;

        if (lane < K_)
            out[OUT_ALPHA + (size_t)bt * K_ + lane] = e0 * inv;
        if (lane + 32 < K_)
            out[OUT_ALPHA + (size_t)bt * K_ + lane + 32] = e1 * inv;
        if (lane == 0)
            out[OUT_BETA + bt] = beta;
    }
}

// ---------------------------------------------------------------------------
// c_t via tensor cores: per batch, c_t[256,512] = alpha[256,49] @ V[49,512],
// then c_hat = c_t + beta*(s_t - c_t) in the epilogue.
// CTA tile 128x64, K padded 49->56 (zero-fill). Grid (8 n-tiles, 32 m-tiles).
// Reads alpha/beta from out (written by fused_z_kernel).
// ---------------------------------------------------------------------------
__global__ __launch_bounds__(256)
void ct_gemm_kernel(const float* __restrict__ V, const float* __restrict__ s_t,
                    float* __restrict__ out)
{
    __shared__ float As[128 * 60];   // alpha [m][k], stride 60, k padded to 56
    __shared__ float Bs[56 * 72];    // V [k][n], stride 72

    const int nt = blockIdx.x;       // 0..7
    const int mb = blockIdx.y;       // 0..31
    const int b     = mb >> 1;
    const int mbase = (mb & 1) * 128;   // t offset within batch
    const int nbase = nt * 64;

    const int tid  = threadIdx.x;
    const int lane = tid & 31;
    const int wid  = tid >> 5;
    const int g    = lane >> 2;
    const int tg   = lane & 3;
    const int warp_m = (wid >> 2) * 64;    // 0 or 64
    const int warp_n = (wid & 3) * 16;     // 0,16,32,48

    // Load alpha tile [128 x 56] (k >= 49 zeroed)
    const float* __restrict__ arow = out + OUT_ALPHA + ((size_t)b * T_ + mbase) * K_;
    for (int idx = tid; idx < 128 * 56; idx += 256) {
        const int m = idx / 56;
        const int k = idx - m * 56;
        As[m * 60 + k] = (k < K_) ? arow[m * K_ + k] : 0.f;
    }
    // Load V tile [56 x 64] (k >= 49 zeroed)
    for (int idx = tid; idx < 56 * 64; idx += 256) {
        const int k = idx >> 6;
        const int n_ = idx & 63;
        Bs[k * 72 + n_] = (k < K_) ? V[((size_t)b * K_ + k) * 512 + nbase + n_] : 0.f;
    }
    __syncthreads();

    float acc[4][2][4];
    #pragma unroll
    for (int i = 0; i < 4; i++)
        #pragma unroll
        for (int j = 0; j < 2; j++)
            #pragma unroll
            for (int q = 0; q < 4; q++) acc[i][j][q] = 0.f;

    #pragma unroll
    for (int kb = 0; kb < 56; kb += 8) {
        uint32_t af[4][4], bf[2][2];
        #pragma unroll
        for (int mi = 0; mi < 4; mi++) {
            const int m0 = warp_m + mi * 16;
            af[mi][0] = __float_as_uint(As[(m0 + g)     * 60 + kb + tg]);
            af[mi][1] = __float_as_uint(As[(m0 + g + 8) * 60 + kb + tg]);
            af[mi][2] = __float_as_uint(As[(m0 + g)     * 60 + kb + tg + 4]);
            af[mi][3] = __float_as_uint(As[(m0 + g + 8) * 60 + kb + tg + 4]);
        }
        #pragma unroll
        for (int ni = 0; ni < 2; ni++) {
            const int n_ = warp_n + ni * 8 + g;
            bf[ni][0] = __float_as_uint(Bs[(kb + tg)     * 72 + n_]);
            bf[ni][1] = __float_as_uint(Bs[(kb + tg + 4) * 72 + n_]);
        }
        #pragma unroll
        for (int mi = 0; mi < 4; mi++)
            #pragma unroll
            for (int ni = 0; ni < 2; ni++) {
                asm volatile(
                    "mma.sync.aligned.m16n8k8.row.col.f32.tf32.tf32.f32 "
                    "{%0,%1,%2,%3}, {%4,%5,%6,%7}, {%8,%9}, {%0,%1,%2,%3};"
                    : "+f"(acc[mi][ni][0]), "+f"(acc[mi][ni][1]),
                      "+f"(acc[mi][ni][2]), "+f"(acc[mi][ni][3])
                    : "r"(af[mi][0]), "r"(af[mi][1]), "r"(af[mi][2]), "r"(af[mi][3]),
                      "r"(bf[ni][0]), "r"(bf[ni][1]));
            }
    }

    // Epilogue: blend with s_t using per-row beta, write c_hat.
    #pragma unroll
    for (int mi = 0; mi < 4; mi++) {
        const int t0 = mbase + warp_m + mi * 16 + g;
        const int t1 = t0 + 8;
        const int bt0 = b * T_ + t0;
        const int bt1 = b * T_ + t1;
        const float beta0 = out[OUT_BETA + bt0];
        const float beta1 = out[OUT_BETA + bt1];
        #pragma unroll
        for (int ni = 0; ni < 2; ni++) {
            const int c = nbase + warp_n + ni * 8 + tg * 2;
            {
                const float2 sv = *reinterpret_cast<const float2*>(&s_t[(size_t)bt0 * 512 + c]);
                float2 o;
                o.x = fmaf(beta0, sv.x - acc[mi][ni][0], acc[mi][ni][0]);
                o.y = fmaf(beta0, sv.y - acc[mi][ni][1], acc[mi][ni][1]);
                *reinterpret_cast<float2*>(&out[(size_t)bt0 * 512 + c]) = o;
            }
            {
                const float2 sv = *reinterpret_cast<const float2*>(&s_t[(size_t)bt1 * 512 + c]);
                float2 o;
                o.x = fmaf(beta1, sv.x - acc[mi][ni][2], acc[mi][ni][2]);
                o.y = fmaf(beta1, sv.y - acc[mi][ni][3], acc[mi][ni][3]);
                *reinterpret_cast<float2*>(&out[(size_t)bt1 * 512 + c]) = o;
            }
        }
    }
}

// ---------------------------------------------------------------------------
extern "C" void kernel_launch(void* const* d_in, const int* in_sizes, int n_in,
                              void* d_out, int out_size)
{
    (void)in_sizes; (void)n_in; (void)out_size;
    const float* V   = (const float*)d_in[0];
    const float* h_t = (const float*)d_in[1];
    const float* s_t = (const float*)d_in[2];
    const float* Wv  = (const float*)d_in[3];
    const float* bv  = (const float*)d_in[4];
    const float* Wg  = (const float*)d_in[5];
    const float* bg  = (const float*)d_in[6];
    const float* Ws  = (const float*)d_in[7];
    const float* bs  = (const float*)d_in[8];
    const float* Wh  = (const float*)d_in[9];
    const float* bh  = (const float*)d_in[10];
    float* out = (float*)d_out;

    gemm3_tf32_kernel<<<dim3(4, 71), 256>>>(V, h_t, s_t, Wv, bv, Wg, bg, Ws, bs);
    fused_z_kernel<<<dim3(B_ * T_), 128>>>(Wh, bh, out);
    ct_gemm_kernel<<<dim3(8, 32), 256>>>(V, s_t, out);
}